// round 14
// baseline (speedup 1.0000x reference)
#include <cuda_runtime.h>
#include <cuda_fp16.h>
#include <cstdint>
#include <math_constants.h>

#define N_VEC 65536
#define D 64
#define K 1024
#define MARGIN 2.5e-4f
#define OUT_E_OFF ((size_t)N_VEC * D)
#define OUT_S_OFF (OUT_E_OFF + (size_t)N_VEC * K)

#define APAD 72                    // fp16 elems per padded row (144B)
#define BPAD 72
// M1 smem layout (per CTA, 2 CTAs/SM): sBb 2KB | A 256*144 | B 512*144
#define OFF_SBB 0
#define OFF_A   2048
#define OFF_B   (2048 + 36864)     // 38912
#define SMEM_TOTAL (OFF_B + 73728) // 112640

__device__ float  g_B[K];
__device__ __align__(16) __half g_ehf[K * BPAD];
__device__ int    g_cnt;
__device__ int    g_list[N_VEC];
__device__ int    g_idx[N_VEC];
__device__ __align__(16) uint4 g_k4[2][N_VEC];  // per-half sorted top-4 PAIR keys
__device__ float  g_part2[512];
__device__ float  g_fix;

// key: biased score (+1.0 => positive => raw-bit orderable), low 10 bits = 1023-k
__device__ __forceinline__ float unpackkey(uint32_t key) {
    return __uint_as_float(key & 0xFFFFFC00u);
}
// branchless insert into descending top-4 (7 IMNMX)
#define INSK(S, t0) { uint32_t _t = (t0), _u; \
    _u = max((S)[0], _t); _t = min((S)[0], _t); (S)[0] = _u; \
    _u = max((S)[1], _t); _t = min((S)[1], _t); (S)[1] = _u; \
    _u = max((S)[2], _t); _t = min((S)[2], _t); (S)[2] = _u; \
    (S)[3] = max((S)[3], _t); }

#define MMA(c, a, bb0, bb1) asm volatile( \
    "mma.sync.aligned.m16n8k16.row.col.f32.f16.f16.f32 " \
    "{%0,%1,%2,%3}, {%4,%5,%6,%7}, {%8,%9}, {%0,%1,%2,%3};" \
    : "+f"(c[0]), "+f"(c[1]), "+f"(c[2]), "+f"(c[3]) \
    : "r"(a[0]), "r"(a[1]), "r"(a[2]), "r"(a[3]), "r"(bb0), "r"(bb1))

#define LOADB(B0, B1, NT) { \
    const int brw = ((NT) * 8 + g) * 36; \
    _Pragma("unroll") \
    for (int ks = 0; ks < 4; ks++) { \
        (B0)[ks] = Bw[brw + ks * 8 + tig]; \
        (B1)[ks] = Bw[brw + ks * 8 + tig + 4]; \
    } }

// one step: 4 MMAs; per row-slot pack the 2 col scores, keep PAIRMAX key only
#define STEP(B0, B1, NT) { \
    float c[4] = {0.f, 0.f, 0.f, 0.f}; \
    _Pragma("unroll") \
    for (int ks = 0; ks < 4; ks++) MMA(c, af[ks], (B0)[ks], (B1)[ks]); \
    const int k0l = (NT) * 8 + tig * 2; \
    const float2 bb = *(const float2*)(sBb + k0l); \
    const uint32_t kv0 = kvbase - (uint32_t)k0l; \
    float s; uint32_t k0, k1, pm; \
    s = fmaf(2.f, c[0], bb.x); k0 = (__float_as_uint(s) & 0xFFFFFC00u) | kv0; \
    s = fmaf(2.f, c[1], bb.y); k1 = (__float_as_uint(s) & 0xFFFFFC00u) | (kv0 - 1); \
    pm = max(k0, k1); INSK(S[0], pm); \
    s = fmaf(2.f, c[2], bb.x); k0 = (__float_as_uint(s) & 0xFFFFFC00u) | kv0; \
    s = fmaf(2.f, c[3], bb.y); k1 = (__float_as_uint(s) & 0xFFFFFC00u) | (kv0 - 1); \
    pm = max(k0, k1); INSK(S[1], pm); }

// ---------------- prep: g_B (exact chain) + padded fp16 codebook ----------
__global__ void vq_prep(const float* __restrict__ emb) {
    int k = blockIdx.x * blockDim.x + threadIdx.x;    // 8 x 128 = 1024
    float v[D];
    const float4* r4 = (const float4*)(emb + (size_t)k * D);
    #pragma unroll
    for (int j = 0; j < 16; j++) {
        float4 t = r4[j];
        v[4*j] = t.x; v[4*j+1] = t.y; v[4*j+2] = t.z; v[4*j+3] = t.w;
    }
    float bb = 0.f;
    #pragma unroll
    for (int d = 0; d < D; d++) bb += v[d] * v[d];
    g_B[k] = bb;
    __half2* eb = (__half2*)(g_ehf + (size_t)k * BPAD);
    #pragma unroll
    for (int j = 0; j < 32; j++)
        eb[j] = __floats2half2_rn(v[2*j], v[2*j+1]);
    #pragma unroll
    for (int j = 32; j < 36; j++)
        eb[j] = __floats2half2_rn(0.f, 0.f);
    if (k == 0) { g_cnt = 0; g_fix = 0.f; }
}

// ---------------- M1: K-split HMMA prefilter, pair keys, 2 CTAs/SM --------
__global__ __launch_bounds__(512, 2) void vq_m1(
    const float* __restrict__ xg)
{
    extern __shared__ char sm[];
    float*    sBb = (float*)(sm + OFF_SBB);
    uint32_t* Aw  = (uint32_t*)(sm + OFF_A);   // 36 words per padded row
    uint32_t* Bw  = (uint32_t*)(sm + OFF_B);

    const int tid = threadIdx.x;
    const int warp = tid >> 5, lane = tid & 31;
    const int g = lane >> 2, tig = lane & 3;
    const int bid = blockIdx.x;
    const int n0 = (bid >> 1) * 256;
    const int kh = bid & 1;
    const uint32_t kvbase = 1023u - (uint32_t)(kh * 512);

    if (tid < 512) sBb[tid] = 1.0f - g_B[kh * 512 + tid];
    { // stage A: 256 rows of x -> fp16 padded
        const float4* x4 = (const float4*)(xg + (size_t)n0 * D);
        #pragma unroll
        for (int u = 0; u < 8; u++) {
            int i = tid + u * 512;
            float4 v = x4[i];
            int row = i >> 4, j = i & 15;
            __half2* p = (__half2*)((__half*)(sm + OFF_A) + row * APAD + j * 4);
            p[0] = __floats2half2_rn(v.x, v.y);
            p[1] = __floats2half2_rn(v.z, v.w);
        }
    }
    { // stage B: this half's 512 codebook rows (already fp16-padded)
        const float4* e4 = (const float4*)(g_ehf + (size_t)kh * 512 * BPAD);
        float4* s4 = (float4*)(sm + OFF_B);
        #pragma unroll
        for (int u = 0; u < 9; u++) {
            int i = tid + u * 512;
            s4[i] = e4[i];
        }
    }
    __syncthreads();

    // A fragments: this warp's 16 rows
    const int rbase = warp * 16;
    uint32_t af[4][4];
    {
        int r0w = (rbase + g) * 36;
        #pragma unroll
        for (int ks = 0; ks < 4; ks++) {
            int kw = ks * 8 + tig;
            af[ks][0] = Aw[r0w + kw];
            af[ks][1] = Aw[r0w + 288 + kw];      // +8 rows
            af[ks][2] = Aw[r0w + kw + 4];
            af[ks][3] = Aw[r0w + 288 + kw + 4];
        }
    }
    uint32_t S[2][4];
    #pragma unroll
    for (int j = 0; j < 2; j++)
        #pragma unroll
        for (int p = 0; p < 4; p++) S[j][p] = 0u;

    uint32_t bA0[4], bA1[4], bB0[4], bB1[4];
    LOADB(bA0, bA1, 0);
    #pragma unroll 2
    for (int nt = 0; nt < 64; nt += 2) {
        LOADB(bB0, bB1, nt + 1);
        STEP(bA0, bA1, nt);
        if (nt + 2 < 64) LOADB(bA0, bA1, nt + 2);
        STEP(bB0, bB1, nt + 1);
    }
    // quad merge (pair keys; disjoint pairs across lanes)
    #pragma unroll
    for (int dd = 1; dd <= 2; dd <<= 1) {
        #pragma unroll
        for (int j = 0; j < 2; j++) {
            uint32_t ns[4];
            #pragma unroll
            for (int p = 0; p < 4; p++)
                ns[p] = __shfl_xor_sync(0xffffffffu, S[j][p], dd);
            #pragma unroll
            for (int p = 0; p < 4; p++) INSK(S[j], ns[p]);
        }
    }
    if (tig < 2) {
        const int r = rbase + g + tig * 8;
        const int n = n0 + r;
        uint32_t* Ss = S[tig];
        g_k4[kh][n] = make_uint4(Ss[0], Ss[1], Ss[2], Ss[3]);
    }
}

// ---------------- M2: merge halves + exact rescore (8 cands) + epilogue ---
__global__ __launch_bounds__(128) void vq_m2(
    const float* __restrict__ xg, const float* __restrict__ emb, float* __restrict__ out)
{
    __shared__ float sX[128 * 68];   // staged x tile (pad stride 68)
    __shared__ int   sIdx[128];
    __shared__ float sW[4];
    const int tid = threadIdx.x, lane = tid & 31, warp = tid >> 5;
    const int n0 = blockIdx.x * 128;
    const int n = n0 + tid;

    // stage x tile once, linear coalesced
    {
        const float4* x4 = (const float4*)(xg + (size_t)n0 * D);
        #pragma unroll
        for (int u = 0; u < 16; u++) {
            int i = tid + u * 128;
            float4 v = x4[i];
            int r = i >> 4, c4 = i & 15;
            *(float4*)(sX + r * 68 + c4 * 4) = v;
        }
    }
    __syncthreads();

    // merge the two per-half sorted top-4 pair keys -> global top-4 pairs
    uint4 ka = g_k4[0][n], kb = g_k4[1][n];
    uint32_t S[4] = {ka.x, ka.y, ka.z, ka.w};
    INSK(S, kb.x); INSK(S, kb.y); INSK(S, kb.z); INSK(S, kb.w);
    const bool fb = (unpackkey(S[3]) >= unpackkey(S[0]) - MARGIN);
    int cand[8];
    #pragma unroll
    for (int q = 0; q < 4; q++) {
        int base = 1023 - (int)(S[q] & 1023u);
        cand[2*q]     = base;
        cand[2*q + 1] = base ^ 1;    // pair partner (pairs are (even, odd))
    }
    if (fb) { int sl = atomicAdd(&g_cnt, 1); g_list[sl] = n; }

    // xv from smem (bit-identical copy of x row)
    float xv[64];
    {
        const float4* xr = (const float4*)(sX + tid * 68);
        #pragma unroll
        for (int j = 0; j < 16; j++) {
            float4 v = xr[j];
            xv[4*j] = v.x; xv[4*j+1] = v.y; xv[4*j+2] = v.z; xv[4*j+3] = v.w;
        }
    }
    float Av = 0.f;
    #pragma unroll
    for (int d = 0; d < D; d++) Av = fmaf(xv[d], xv[d], Av);

    // exact rescore of 8 candidates; (distbits, k) u64-min == first-min over
    // ascending k with strict < (dist > 0 here => bits orderable)
    unsigned long long bk = ~0ull;
    #pragma unroll
    for (int q = 0; q < 8; q++) {
        int idx = cand[q];
        const float4* er = (const float4*)(emb + (size_t)idx * D);
        float a = 0.f;
        #pragma unroll
        for (int j = 0; j < 16; j++) {
            float4 v = er[j];
            a = fmaf(xv[4*j],   v.x, a);
            a = fmaf(xv[4*j+1], v.y, a);
            a = fmaf(xv[4*j+2], v.z, a);
            a = fmaf(xv[4*j+3], v.w, a);
        }
        float ddv = (Av + g_B[idx]) - 2.f * a;
        unsigned long long key =
            ((unsigned long long)__float_as_uint(ddv) << 32) | (unsigned)idx;
        bk = min(bk, key);
    }
    const int bidx = (int)(bk & 0xffffffffu);
    sIdx[tid] = bidx;
    g_idx[n] = bidx;
    __syncthreads();

    // quantized_st + loss: linear coalesced, x from smem
    float ls = 0.f;
    {
        float4* qo = (float4*)(out + (size_t)n0 * D);
        #pragma unroll
        for (int it = 0; it < 16; it++) {
            int i = tid + it * 128;
            int r = i >> 4, c4 = i & 15;
            int idx = sIdx[r];
            float4 xw = *(const float4*)(sX + r * 68 + c4 * 4);
            float4 e4 = ((const float4*)(emb + (size_t)idx * D))[c4];
            float dx = e4.x - xw.x, dy = e4.y - xw.y;
            float dz = e4.z - xw.z, dw = e4.w - xw.w;
            __stcs(&qo[i], make_float4(xw.x + dx, xw.y + dy, xw.z + dz, xw.w + dw));
            ls += dx*dx + dy*dy + dz*dz + dw*dw;
        }
    }
    #pragma unroll
    for (int o = 16; o; o >>= 1) ls += __shfl_down_sync(0xffffffffu, ls, o);
    if (lane == 0) sW[warp] = ls;
    __syncthreads();
    if (tid == 0) g_part2[blockIdx.x] = sW[0] + sW[1] + sW[2] + sW[3];
}

// ---------------- fallback: chunked smem, 1 vec/warp, MLP loads -----------
#define FCHUNK 128
#define FSTRIDE 68
#define FBLOCKS 296
__global__ __launch_bounds__(256) void vq_fallback(
    const float* __restrict__ xg, const float* __restrict__ emb, float* __restrict__ out)
{
    __shared__ float sC[FCHUNK * FSTRIDE];   // 34816B
    const int cnt = g_cnt;
    if (blockIdx.x * 8 >= cnt) return;
    const int tid = threadIdx.x, warp = tid >> 5, lane = tid & 31;
    const int nwg = FBLOCKS * 8;
    const int rounds = (cnt + nwg - 1) / nwg;
    for (int rd = 0; rd < rounds; rd++) {
        if (rd * nwg + blockIdx.x * 8 >= cnt) break;
        const int it = rd * nwg + blockIdx.x * 8 + warp;
        const bool act = it < cnt;
        const int n = act ? g_list[it] : 0;
        float xv[64];
        float Av = 0.f;
        if (act) {
            const float4* xr = (const float4*)(xg + (size_t)n * D);
            #pragma unroll
            for (int j = 0; j < 16; j++) {
                float4 v = xr[j];
                xv[4*j] = v.x; xv[4*j+1] = v.y; xv[4*j+2] = v.z; xv[4*j+3] = v.w;
            }
            #pragma unroll
            for (int d = 0; d < D; d++) Av = fmaf(xv[d], xv[d], Av);
        }
        float best = CUDART_INF_F; int bidx = 0;
        for (int ch = 0; ch < K / FCHUNK; ch++) {
            float4 ld[8];
            const float4* e4 = (const float4*)(emb + (size_t)ch * FCHUNK * D);
            #pragma unroll
            for (int u = 0; u < 8; u++) ld[u] = e4[tid + u * 256];
            __syncthreads();
            #pragma unroll
            for (int u = 0; u < 8; u++) {
                int i = tid + u * 256;
                int row = i >> 4, j = i & 15;
                *(float4*)(sC + row * FSTRIDE + j * 4) = ld[u];
            }
            __syncthreads();
            if (act) {
                #pragma unroll
                for (int cj = 0; cj < FCHUNK / 32; cj++) {
                    int c = lane + cj * 32;
                    int k = ch * FCHUNK + c;
                    const float4* er = (const float4*)(sC + c * FSTRIDE);
                    float a = 0.f;
                    #pragma unroll
                    for (int j = 0; j < 16; j++) {
                        float4 v = er[j];
                        a = fmaf(xv[4*j],   v.x, a);
                        a = fmaf(xv[4*j+1], v.y, a);
                        a = fmaf(xv[4*j+2], v.z, a);
                        a = fmaf(xv[4*j+3], v.w, a);
                    }
                    float ddv = (Av + g_B[k]) - 2.f * a;
                    if (ddv < best) { best = ddv; bidx = k; }
                }
            }
        }
        if (act) {
            unsigned long long key =
                ((unsigned long long)__float_as_uint(best) << 32) | (unsigned)bidx;
            #pragma unroll
            for (int o = 16; o; o >>= 1) {
                unsigned long long k2 = __shfl_down_sync(0xffffffffu, key, o);
                if (k2 < key) key = k2;
            }
            key = __shfl_sync(0xffffffffu, key, 0);
            const int idx = (int)(key & 0xffffffffu);
            const int old = g_idx[n];
            if (idx != old) {
                if (lane == 0) g_idx[n] = idx;
                float lsn = 0.f, lso = 0.f;
                if (lane < 16) {
                    float4 e4 = ((const float4*)(emb + (size_t)idx * D))[lane];
                    float4 o4 = ((const float4*)(emb + (size_t)old * D))[lane];
                    float xx = xv[4*lane], xy = xv[4*lane+1], xz = xv[4*lane+2], xw2 = xv[4*lane+3];
                    float dx = e4.x-xx, dy = e4.y-xy, dz = e4.z-xz, dw = e4.w-xw2;
                    ((float4*)(out + (size_t)n * D))[lane] =
                        make_float4(xx+dx, xy+dy, xz+dz, xw2+dw);
                    lsn = dx*dx + dy*dy + dz*dz + dw*dw;
                    float ox = o4.x-xx, oy = o4.y-xy, oz = o4.z-xz, ow = o4.w-xw2;
                    lso = ox*ox + oy*oy + oz*oz + ow*ow;
                }
                #pragma unroll
                for (int o = 16; o; o >>= 1) {
                    lsn += __shfl_down_sync(0xffffffffu, lsn, o);
                    lso += __shfl_down_sync(0xffffffffu, lso, o);
                }
                if (lane == 0) atomicAdd(&g_fix, lsn - lso);
            }
        }
    }
}

// ---------------- one-hot encodings: dedicated streaming kernel -----------
__global__ __launch_bounds__(512) void vq_onehot(float* __restrict__ out) {
    __shared__ int sI[64];
    const int r0 = blockIdx.x * 64;       // grid 1024
    if (threadIdx.x < 64) sI[threadIdx.x] = g_idx[r0 + threadIdx.x];
    __syncthreads();
    float* eout = out + OUT_E_OFF;
    #pragma unroll 8
    for (int i = threadIdx.x; i < 64 * 256; i += 512) {
        int r = i >> 8, c4 = i & 255;
        int idx = sI[r];
        float4 v = make_float4(0.f, 0.f, 0.f, 0.f);
        if ((idx >> 2) == c4) ((float*)&v)[idx & 3] = 1.f;
        __stcs(&((float4*)(eout + (size_t)(r0 + r) * K))[c4], v);
    }
}

// ---------------- finalize: 512 partials + fix ----------------------------
__global__ void vq_finalize(float* __restrict__ out) {
    __shared__ double sR[256];
    int tid = threadIdx.x;   // 256
    sR[tid] = (double)g_part2[tid] + (double)g_part2[tid + 256];
    __syncthreads();
    #pragma unroll
    for (int st = 128; st; st >>= 1) {
        if (tid < st) sR[tid] += sR[tid + st];
        __syncthreads();
    }
    if (tid == 0) {
        double tot = sR[0] + (double)g_fix;
        float cb = (float)(tot / (double)((size_t)N_VEC * D));
        out[OUT_S_OFF + 0] = cb + 0.25f * cb;
        out[OUT_S_OFF + 1] = cb;
        out[OUT_S_OFF + 2] = cb;
    }
}

extern "C" void kernel_launch(void* const* d_in, const int* in_sizes, int n_in,
                              void* d_out, int out_size) {
    const float* x   = (const float*)d_in[0];
    const float* emb = (const float*)d_in[1];
    float* out = (float*)d_out;
    cudaFuncSetAttribute(vq_m1, cudaFuncAttributeMaxDynamicSharedMemorySize, SMEM_TOTAL);
    vq_prep<<<8, 128>>>(emb);
    vq_m1<<<512, 512, SMEM_TOTAL>>>(x);
    vq_m2<<<512, 128>>>(x, emb, out);
    vq_fallback<<<FBLOCKS, 256>>>(x, emb, out);
    vq_onehot<<<N_VEC / 64, 512>>>(out);
    vq_finalize<<<1, 256>>>(out);
}

// round 15
// speedup vs baseline: 1.0765x; 1.0765x over previous
#include <cuda_runtime.h>
#include <cuda_fp16.h>
#include <cstdint>
#include <math_constants.h>

#define N_VEC 65536
#define D 64
#define K 1024
#define MARGIN 5e-5f
#define OUT_E_OFF ((size_t)N_VEC * D)
#define OUT_S_OFF (OUT_E_OFF + (size_t)N_VEC * K)

#define APAD 72                    // fp16 elems per padded row (144B)
#define BPAD 72
// M1 smem layout (per CTA, 2 CTAs/SM): sBb 2KB | A 256*144 | B 512*144
#define OFF_SBB 0
#define OFF_A   2048
#define OFF_B   (2048 + 36864)     // 38912
#define SMEM_TOTAL (OFF_B + 73728) // 112640

__device__ float  g_B[K];
__device__ __align__(16) __half g_ehf[K * BPAD];
__device__ int    g_cnt;
__device__ int    g_list[N_VEC];
__device__ int    g_idx[N_VEC];
__device__ __align__(16) uint4 g_k4[2][N_VEC];  // per-half sorted top-4 keys
__device__ float  g_part2[512];
__device__ float  g_fix;

// key: biased score (+1.0 => positive => raw-bit orderable), low 10 bits = 1023-k
__device__ __forceinline__ float unpackkey(uint32_t key) {
    return __uint_as_float(key & 0xFFFFFC00u);
}
// branchless insert into descending top-4 (7 IMNMX)
#define INSK(S, t0) { uint32_t _t = (t0), _u; \
    _u = max((S)[0], _t); _t = min((S)[0], _t); (S)[0] = _u; \
    _u = max((S)[1], _t); _t = min((S)[1], _t); (S)[1] = _u; \
    _u = max((S)[2], _t); _t = min((S)[2], _t); (S)[2] = _u; \
    (S)[3] = max((S)[3], _t); }

#define MMA(c, a, bb0, bb1) asm volatile( \
    "mma.sync.aligned.m16n8k16.row.col.f32.f16.f16.f32 " \
    "{%0,%1,%2,%3}, {%4,%5,%6,%7}, {%8,%9}, {%0,%1,%2,%3};" \
    : "+f"(c[0]), "+f"(c[1]), "+f"(c[2]), "+f"(c[3]) \
    : "r"(a[0]), "r"(a[1]), "r"(a[2]), "r"(a[3]), "r"(bb0), "r"(bb1))

#define CSWP(a, b) { if ((a) > (b)) { int _t = (a); (a) = (b); (b) = _t; } }

#define LOADB(B0, B1, NT) { \
    const int brw = ((NT) * 8 + g) * 36; \
    _Pragma("unroll") \
    for (int ks = 0; ks < 4; ks++) { \
        (B0)[ks] = Bw[brw + ks * 8 + tig]; \
        (B1)[ks] = Bw[brw + ks * 8 + tig + 4]; \
    } }

// one step: 4 MMAs in TWO independent chains (halved dependency depth),
// 4 scores (rows g, g+8 x 2 cols), cheap-pack, insert
#define STEP(B0, B1, NT) { \
    float ca[4] = {0.f, 0.f, 0.f, 0.f}, cb[4] = {0.f, 0.f, 0.f, 0.f}; \
    MMA(ca, af[0], (B0)[0], (B1)[0]); \
    MMA(cb, af[1], (B0)[1], (B1)[1]); \
    MMA(ca, af[2], (B0)[2], (B1)[2]); \
    MMA(cb, af[3], (B0)[3], (B1)[3]); \
    const int k0l = (NT) * 8 + tig * 2; \
    const float2 bb = *(const float2*)(sBb + k0l); \
    const uint32_t kv0 = kvbase - (uint32_t)k0l; \
    float s; uint32_t key; \
    s = fmaf(2.f, ca[0] + cb[0], bb.x); key = (__float_as_uint(s) & 0xFFFFFC00u) | kv0;       INSK(S[0], key); \
    s = fmaf(2.f, ca[1] + cb[1], bb.y); key = (__float_as_uint(s) & 0xFFFFFC00u) | (kv0 - 1); INSK(S[0], key); \
    s = fmaf(2.f, ca[2] + cb[2], bb.x); key = (__float_as_uint(s) & 0xFFFFFC00u) | kv0;       INSK(S[1], key); \
    s = fmaf(2.f, ca[3] + cb[3], bb.y); key = (__float_as_uint(s) & 0xFFFFFC00u) | (kv0 - 1); INSK(S[1], key); }

// ---------------- prep: g_B (exact chain) + padded fp16 codebook ----------
__global__ void vq_prep(const float* __restrict__ emb) {
    int k = blockIdx.x * blockDim.x + threadIdx.x;    // 8 x 128 = 1024
    float v[D];
    const float4* r4 = (const float4*)(emb + (size_t)k * D);
    #pragma unroll
    for (int j = 0; j < 16; j++) {
        float4 t = r4[j];
        v[4*j] = t.x; v[4*j+1] = t.y; v[4*j+2] = t.z; v[4*j+3] = t.w;
    }
    float bb = 0.f;
    #pragma unroll
    for (int d = 0; d < D; d++) bb += v[d] * v[d];
    g_B[k] = bb;
    __half2* eb = (__half2*)(g_ehf + (size_t)k * BPAD);
    #pragma unroll
    for (int j = 0; j < 32; j++)
        eb[j] = __floats2half2_rn(v[2*j], v[2*j+1]);
    #pragma unroll
    for (int j = 32; j < 36; j++)
        eb[j] = __floats2half2_rn(0.f, 0.f);
    if (k == 0) { g_cnt = 0; g_fix = 0.f; }
}

// ---------------- M1: K-split HMMA prefilter, 2 CTAs/SM -------------------
__global__ __launch_bounds__(512, 2) void vq_m1(
    const float* __restrict__ xg)
{
    extern __shared__ char sm[];
    float*    sBb = (float*)(sm + OFF_SBB);
    uint32_t* Aw  = (uint32_t*)(sm + OFF_A);   // 36 words per padded row
    uint32_t* Bw  = (uint32_t*)(sm + OFF_B);

    const int tid = threadIdx.x;
    const int warp = tid >> 5, lane = tid & 31;
    const int g = lane >> 2, tig = lane & 3;
    const int bid = blockIdx.x;
    const int n0 = (bid >> 1) * 256;
    const int kh = bid & 1;
    const uint32_t kvbase = 1023u - (uint32_t)(kh * 512);

    if (tid < 512) sBb[tid] = 1.0f - g_B[kh * 512 + tid];
    { // stage A: 256 rows of x -> fp16 padded
        const float4* x4 = (const float4*)(xg + (size_t)n0 * D);
        #pragma unroll
        for (int u = 0; u < 8; u++) {
            int i = tid + u * 512;
            float4 v = x4[i];
            int row = i >> 4, j = i & 15;
            __half2* p = (__half2*)((__half*)(sm + OFF_A) + row * APAD + j * 4);
            p[0] = __floats2half2_rn(v.x, v.y);
            p[1] = __floats2half2_rn(v.z, v.w);
        }
    }
    { // stage B: this half's 512 codebook rows (already fp16-padded)
        const float4* e4 = (const float4*)(g_ehf + (size_t)kh * 512 * BPAD);
        float4* s4 = (float4*)(sm + OFF_B);
        #pragma unroll
        for (int u = 0; u < 9; u++) {
            int i = tid + u * 512;
            s4[i] = e4[i];
        }
    }
    __syncthreads();

    // A fragments: this warp's 16 rows
    const int rbase = warp * 16;
    uint32_t af[4][4];
    {
        int r0w = (rbase + g) * 36;
        #pragma unroll
        for (int ks = 0; ks < 4; ks++) {
            int kw = ks * 8 + tig;
            af[ks][0] = Aw[r0w + kw];
            af[ks][1] = Aw[r0w + 288 + kw];      // +8 rows
            af[ks][2] = Aw[r0w + kw + 4];
            af[ks][3] = Aw[r0w + 288 + kw + 4];
        }
    }
    uint32_t S[2][4];
    #pragma unroll
    for (int j = 0; j < 2; j++)
        #pragma unroll
        for (int p = 0; p < 4; p++) S[j][p] = 0u;

    uint32_t bA0[4], bA1[4], bB0[4], bB1[4];
    LOADB(bA0, bA1, 0);
    #pragma unroll 2
    for (int nt = 0; nt < 64; nt += 2) {
        LOADB(bB0, bB1, nt + 1);
        STEP(bA0, bA1, nt);
        if (nt + 2 < 64) LOADB(bA0, bA1, nt + 2);
        STEP(bB0, bB1, nt + 1);
    }
    // quad merge
    #pragma unroll
    for (int dd = 1; dd <= 2; dd <<= 1) {
        #pragma unroll
        for (int j = 0; j < 2; j++) {
            uint32_t ns[4];
            #pragma unroll
            for (int p = 0; p < 4; p++)
                ns[p] = __shfl_xor_sync(0xffffffffu, S[j][p], dd);
            #pragma unroll
            for (int p = 0; p < 4; p++) INSK(S[j], ns[p]);
        }
    }
    if (tig < 2) {
        const int r = rbase + g + tig * 8;
        const int n = n0 + r;
        uint32_t* Ss = S[tig];
        g_k4[kh][n] = make_uint4(Ss[0], Ss[1], Ss[2], Ss[3]);
    }
}

// ---------------- M2: merge halves + exact rescore + epilogue -------------
__global__ __launch_bounds__(128) void vq_m2(
    const float* __restrict__ xg, const float* __restrict__ emb, float* __restrict__ out)
{
    __shared__ int   sIdx[128];
    __shared__ float sW[4];
    const int tid = threadIdx.x, lane = tid & 31, warp = tid >> 5;
    const int n0 = blockIdx.x * 128;
    const int n = n0 + tid;

    // merge the two per-half sorted top-4s -> global top-4
    uint4 ka = g_k4[0][n], kb = g_k4[1][n];
    uint32_t S[4] = {ka.x, ka.y, ka.z, ka.w};
    INSK(S, kb.x); INSK(S, kb.y); INSK(S, kb.z); INSK(S, kb.w);
    const bool fb = (unpackkey(S[3]) >= unpackkey(S[0]) - MARGIN);
    int ci[4] = { 1023 - (int)(S[0] & 1023u), 1023 - (int)(S[1] & 1023u),
                  1023 - (int)(S[2] & 1023u), 1023 - (int)(S[3] & 1023u) };
    CSWP(ci[0], ci[1]); CSWP(ci[2], ci[3]);
    CSWP(ci[0], ci[2]); CSWP(ci[1], ci[3]); CSWP(ci[1], ci[2]);
    if (fb) { int sl = atomicAdd(&g_cnt, 1); g_list[sl] = n; }

    float xv[64];
    {
        const float4* xr = (const float4*)(xg + (size_t)n * D);
        #pragma unroll
        for (int j = 0; j < 16; j++) {
            float4 v = xr[j];
            xv[4*j] = v.x; xv[4*j+1] = v.y; xv[4*j+2] = v.z; xv[4*j+3] = v.w;
        }
    }
    float Av = 0.f;
    #pragma unroll
    for (int d = 0; d < D; d++) Av = fmaf(xv[d], xv[d], Av);

    // exact rescore (validated round-0 fl chain, ascending-k strict <)
    float best = CUDART_INF_F; int bidx = 0;
    #pragma unroll
    for (int q = 0; q < 4; q++) {
        int idx = ci[q];
        const float4* er = (const float4*)(emb + (size_t)idx * D);
        float a = 0.f;
        #pragma unroll
        for (int j = 0; j < 16; j++) {
            float4 v = er[j];
            a = fmaf(xv[4*j],   v.x, a);
            a = fmaf(xv[4*j+1], v.y, a);
            a = fmaf(xv[4*j+2], v.z, a);
            a = fmaf(xv[4*j+3], v.w, a);
        }
        float ddv = (Av + g_B[idx]) - 2.f * a;
        if (ddv < best) { best = ddv; bidx = idx; }
    }
    sIdx[tid] = bidx;
    g_idx[n] = bidx;
    __syncthreads();

    // quantized_st + loss: linear coalesced loop over the 128-vector tile
    float ls = 0.f;
    {
        const float4* x4 = (const float4*)(xg + (size_t)n0 * D);
        float4* qo = (float4*)(out + (size_t)n0 * D);
        #pragma unroll
        for (int it = 0; it < 16; it++) {
            int i = tid + it * 128;
            int r = i >> 4, c4 = i & 15;
            int idx = sIdx[r];
            float4 xw = x4[i];
            float4 e4 = ((const float4*)(emb + (size_t)idx * D))[c4];
            float dx = e4.x - xw.x, dy = e4.y - xw.y;
            float dz = e4.z - xw.z, dw = e4.w - xw.w;
            __stcs(&qo[i], make_float4(xw.x + dx, xw.y + dy, xw.z + dz, xw.w + dw));
            ls += dx*dx + dy*dy + dz*dz + dw*dw;
        }
    }
    #pragma unroll
    for (int o = 16; o; o >>= 1) ls += __shfl_down_sync(0xffffffffu, ls, o);
    if (lane == 0) sW[warp] = ls;
    __syncthreads();
    if (tid == 0) g_part2[blockIdx.x] = sW[0] + sW[1] + sW[2] + sW[3];
}

// ---------------- fallback: chunked smem, 1 vec/warp, MLP loads -----------
#define FCHUNK 128
#define FSTRIDE 68
#define FBLOCKS 296
__global__ __launch_bounds__(256) void vq_fallback(
    const float* __restrict__ xg, const float* __restrict__ emb, float* __restrict__ out)
{
    __shared__ float sC[FCHUNK * FSTRIDE];   // 34816B
    const int cnt = g_cnt;
    if (blockIdx.x * 8 >= cnt) return;
    const int tid = threadIdx.x, warp = tid >> 5, lane = tid & 31;
    const int nwg = FBLOCKS * 8;
    const int rounds = (cnt + nwg - 1) / nwg;
    for (int rd = 0; rd < rounds; rd++) {
        if (rd * nwg + blockIdx.x * 8 >= cnt) break;
        const int it = rd * nwg + blockIdx.x * 8 + warp;
        const bool act = it < cnt;
        const int n = act ? g_list[it] : 0;
        float xv[64];
        float Av = 0.f;
        if (act) {
            const float4* xr = (const float4*)(xg + (size_t)n * D);
            #pragma unroll
            for (int j = 0; j < 16; j++) {
                float4 v = xr[j];
                xv[4*j] = v.x; xv[4*j+1] = v.y; xv[4*j+2] = v.z; xv[4*j+3] = v.w;
            }
            #pragma unroll
            for (int d = 0; d < D; d++) Av = fmaf(xv[d], xv[d], Av);
        }
        float best = CUDART_INF_F; int bidx = 0;
        for (int ch = 0; ch < K / FCHUNK; ch++) {
            float4 ld[8];
            const float4* e4 = (const float4*)(emb + (size_t)ch * FCHUNK * D);
            #pragma unroll
            for (int u = 0; u < 8; u++) ld[u] = e4[tid + u * 256];
            __syncthreads();
            #pragma unroll
            for (int u = 0; u < 8; u++) {
                int i = tid + u * 256;
                int row = i >> 4, j = i & 15;
                *(float4*)(sC + row * FSTRIDE + j * 4) = ld[u];
            }
            __syncthreads();
            if (act) {
                #pragma unroll
                for (int cj = 0; cj < FCHUNK / 32; cj++) {
                    int c = lane + cj * 32;
                    int k = ch * FCHUNK + c;
                    const float4* er = (const float4*)(sC + c * FSTRIDE);
                    float a = 0.f;
                    #pragma unroll
                    for (int j = 0; j < 16; j++) {
                        float4 v = er[j];
                        a = fmaf(xv[4*j],   v.x, a);
                        a = fmaf(xv[4*j+1], v.y, a);
                        a = fmaf(xv[4*j+2], v.z, a);
                        a = fmaf(xv[4*j+3], v.w, a);
                    }
                    float ddv = (Av + g_B[k]) - 2.f * a;
                    if (ddv < best) { best = ddv; bidx = k; }
                }
            }
        }
        if (act) {
            unsigned long long key =
                ((unsigned long long)__float_as_uint(best) << 32) | (unsigned)bidx;
            #pragma unroll
            for (int o = 16; o; o >>= 1) {
                unsigned long long k2 = __shfl_down_sync(0xffffffffu, key, o);
                if (k2 < key) key = k2;
            }
            key = __shfl_sync(0xffffffffu, key, 0);
            const int idx = (int)(key & 0xffffffffu);
            const int old = g_idx[n];
            if (idx != old) {
                if (lane == 0) g_idx[n] = idx;
                float lsn = 0.f, lso = 0.f;
                if (lane < 16) {
                    float4 e4 = ((const float4*)(emb + (size_t)idx * D))[lane];
                    float4 o4 = ((const float4*)(emb + (size_t)old * D))[lane];
                    float xx = xv[4*lane], xy = xv[4*lane+1], xz = xv[4*lane+2], xw2 = xv[4*lane+3];
                    float dx = e4.x-xx, dy = e4.y-xy, dz = e4.z-xz, dw = e4.w-xw2;
                    ((float4*)(out + (size_t)n * D))[lane] =
                        make_float4(xx+dx, xy+dy, xz+dz, xw2+dw);
                    lsn = dx*dx + dy*dy + dz*dz + dw*dw;
                    float ox = o4.x-xx, oy = o4.y-xy, oz = o4.z-xz, ow = o4.w-xw2;
                    lso = ox*ox + oy*oy + oz*oz + ow*ow;
                }
                #pragma unroll
                for (int o = 16; o; o >>= 1) {
                    lsn += __shfl_down_sync(0xffffffffu, lsn, o);
                    lso += __shfl_down_sync(0xffffffffu, lso, o);
                }
                if (lane == 0) atomicAdd(&g_fix, lsn - lso);
            }
        }
    }
}

// ---------------- one-hot encodings: dedicated streaming kernel -----------
__global__ __launch_bounds__(512) void vq_onehot(float* __restrict__ out) {
    __shared__ int sI[64];
    const int r0 = blockIdx.x * 64;       // grid 1024
    if (threadIdx.x < 64) sI[threadIdx.x] = g_idx[r0 + threadIdx.x];
    __syncthreads();
    float* eout = out + OUT_E_OFF;
    #pragma unroll 8
    for (int i = threadIdx.x; i < 64 * 256; i += 512) {
        int r = i >> 8, c4 = i & 255;
        int idx = sI[r];
        float4 v = make_float4(0.f, 0.f, 0.f, 0.f);
        if ((idx >> 2) == c4) ((float*)&v)[idx & 3] = 1.f;
        __stcs(&((float4*)(eout + (size_t)(r0 + r) * K))[c4], v);
    }
}

// ---------------- finalize: 512 partials + fix ----------------------------
__global__ void vq_finalize(float* __restrict__ out) {
    __shared__ double sR[256];
    int tid = threadIdx.x;   // 256
    sR[tid] = (double)g_part2[tid] + (double)g_part2[tid + 256];
    __syncthreads();
    #pragma unroll
    for (int st = 128; st; st >>= 1) {
        if (tid < st) sR[tid] += sR[tid + st];
        __syncthreads();
    }
    if (tid == 0) {
        double tot = sR[0] + (double)g_fix;
        float cb = (float)(tot / (double)((size_t)N_VEC * D));
        out[OUT_S_OFF + 0] = cb + 0.25f * cb;
        out[OUT_S_OFF + 1] = cb;
        out[OUT_S_OFF + 2] = cb;
    }
}

extern "C" void kernel_launch(void* const* d_in, const int* in_sizes, int n_in,
                              void* d_out, int out_size) {
    const float* x   = (const float*)d_in[0];
    const float* emb = (const float*)d_in[1];
    float* out = (float*)d_out;
    cudaFuncSetAttribute(vq_m1, cudaFuncAttributeMaxDynamicSharedMemorySize, SMEM_TOTAL);
    vq_prep<<<8, 128>>>(emb);
    vq_m1<<<512, 512, SMEM_TOTAL>>>(x);
    vq_m2<<<512, 128>>>(x, emb, out);
    vq_fallback<<<FBLOCKS, 256>>>(x, emb, out);
    vq_onehot<<<N_VEC / 64, 512>>>(out);
    vq_finalize<<<1, 256>>>(out);
}

// round 16
// speedup vs baseline: 1.1387x; 1.0578x over previous
#include <cuda_runtime.h>
#include <cuda_fp16.h>
#include <cstdint>
#include <math_constants.h>

#define N_VEC 65536
#define D 64
#define K 1024
#define MARGIN 5e-5f
#define OUT_E_OFF ((size_t)N_VEC * D)
#define OUT_S_OFF (OUT_E_OFF + (size_t)N_VEC * K)

#define APAD 72                    // fp16 elems per padded row (144B)
#define BPAD 72
// M1 smem layout (per CTA, 2 CTAs/SM): sBb 2KB | A 256*144 | B 512*144
#define OFF_SBB 0
#define OFF_A   2048
#define OFF_B   (2048 + 36864)     // 38912
#define SMEM_TOTAL (OFF_B + 73728) // 112640

__device__ float  g_B[K];
__device__ __align__(16) __half g_ehf[K * BPAD];
__device__ int    g_cnt;
__device__ int    g_list[N_VEC];
__device__ int    g_idx[N_VEC];
__device__ __align__(16) uint4 g_k4[2][N_VEC];  // per-half sorted top-4 keys
__device__ float  g_part2[512];
__device__ float  g_fix;

// key: biased score (+1.0 => positive => raw-bit orderable), low 10 bits = 1023-k
__device__ __forceinline__ float unpackkey(uint32_t key) {
    return __uint_as_float(key & 0xFFFFFC00u);
}
// branchless insert into descending top-4 (7 IMNMX)
#define INSK(S, t0) { uint32_t _t = (t0), _u; \
    _u = max((S)[0], _t); _t = min((S)[0], _t); (S)[0] = _u; \
    _u = max((S)[1], _t); _t = min((S)[1], _t); (S)[1] = _u; \
    _u = max((S)[2], _t); _t = min((S)[2], _t); (S)[2] = _u; \
    (S)[3] = max((S)[3], _t); }

#define MMA(c, a, bb0, bb1) asm volatile( \
    "mma.sync.aligned.m16n8k16.row.col.f32.f16.f16.f32 " \
    "{%0,%1,%2,%3}, {%4,%5,%6,%7}, {%8,%9}, {%0,%1,%2,%3};" \
    : "+f"(c[0]), "+f"(c[1]), "+f"(c[2]), "+f"(c[3]) \
    : "r"(a[0]), "r"(a[1]), "r"(a[2]), "r"(a[3]), "r"(bb0), "r"(bb1))

#define CSWP(a, b) { if ((a) > (b)) { int _t = (a); (a) = (b); (b) = _t; } }

#define LOADB(B0, B1, NT) { \
    const int brw = ((NT) * 8 + g) * 36; \
    _Pragma("unroll") \
    for (int ks = 0; ks < 4; ks++) { \
        (B0)[ks] = Bw[brw + ks * 8 + tig]; \
        (B1)[ks] = Bw[brw + ks * 8 + tig + 4]; \
    } }

// one step: 4 MMAs in TWO independent chains, 4 scores, cheap-pack, insert
#define STEP(B0, B1, NT) { \
    float ca[4] = {0.f, 0.f, 0.f, 0.f}, cb[4] = {0.f, 0.f, 0.f, 0.f}; \
    MMA(ca, af[0], (B0)[0], (B1)[0]); \
    MMA(cb, af[1], (B0)[1], (B1)[1]); \
    MMA(ca, af[2], (B0)[2], (B1)[2]); \
    MMA(cb, af[3], (B0)[3], (B1)[3]); \
    const int k0l = (NT) * 8 + tig * 2; \
    const float2 bb = *(const float2*)(sBb + k0l); \
    const uint32_t kv0 = kvbase - (uint32_t)k0l; \
    float s; uint32_t key; \
    s = fmaf(2.f, ca[0] + cb[0], bb.x); key = (__float_as_uint(s) & 0xFFFFFC00u) | kv0;       INSK(S[0], key); \
    s = fmaf(2.f, ca[1] + cb[1], bb.y); key = (__float_as_uint(s) & 0xFFFFFC00u) | (kv0 - 1); INSK(S[0], key); \
    s = fmaf(2.f, ca[2] + cb[2], bb.x); key = (__float_as_uint(s) & 0xFFFFFC00u) | kv0;       INSK(S[1], key); \
    s = fmaf(2.f, ca[3] + cb[3], bb.y); key = (__float_as_uint(s) & 0xFFFFFC00u) | (kv0 - 1); INSK(S[1], key); }

// ---------------- prep: g_B (exact chain) + padded fp16 codebook ----------
__global__ void vq_prep(const float* __restrict__ emb) {
    int k = blockIdx.x * blockDim.x + threadIdx.x;    // 8 x 128 = 1024
    float v[D];
    const float4* r4 = (const float4*)(emb + (size_t)k * D);
    #pragma unroll
    for (int j = 0; j < 16; j++) {
        float4 t = r4[j];
        v[4*j] = t.x; v[4*j+1] = t.y; v[4*j+2] = t.z; v[4*j+3] = t.w;
    }
    float bb = 0.f;
    #pragma unroll
    for (int d = 0; d < D; d++) bb += v[d] * v[d];
    g_B[k] = bb;
    __half2* eb = (__half2*)(g_ehf + (size_t)k * BPAD);
    #pragma unroll
    for (int j = 0; j < 32; j++)
        eb[j] = __floats2half2_rn(v[2*j], v[2*j+1]);
    #pragma unroll
    for (int j = 32; j < 36; j++)
        eb[j] = __floats2half2_rn(0.f, 0.f);
    if (k == 0) { g_cnt = 0; g_fix = 0.f; }
}

// ---------------- M1: K-split HMMA prefilter + fused encodings zero-fill --
// Tensor pipe is the bottleneck; DRAM is idle -> stream 512KB of one-hot
// zeros per CTA (fire-and-forget STG.128) that drain during the MMA loop.
__global__ __launch_bounds__(512, 2) void vq_m1(
    const float* __restrict__ xg, float* __restrict__ out)
{
    extern __shared__ char sm[];
    float*    sBb = (float*)(sm + OFF_SBB);
    uint32_t* Aw  = (uint32_t*)(sm + OFF_A);   // 36 words per padded row
    uint32_t* Bw  = (uint32_t*)(sm + OFF_B);

    const int tid = threadIdx.x;
    const int warp = tid >> 5, lane = tid & 31;
    const int g = lane >> 2, tig = lane & 3;
    const int bid = blockIdx.x;
    const int n0 = (bid >> 1) * 256;
    const int kh = bid & 1;
    const uint32_t kvbase = 1023u - (uint32_t)(kh * 512);

    if (tid < 512) sBb[tid] = 1.0f - g_B[kh * 512 + tid];
    { // stage A: 256 rows of x -> fp16 padded
        const float4* x4 = (const float4*)(xg + (size_t)n0 * D);
        #pragma unroll
        for (int u = 0; u < 8; u++) {
            int i = tid + u * 512;
            float4 v = x4[i];
            int row = i >> 4, j = i & 15;
            __half2* p = (__half2*)((__half*)(sm + OFF_A) + row * APAD + j * 4);
            p[0] = __floats2half2_rn(v.x, v.y);
            p[1] = __floats2half2_rn(v.z, v.w);
        }
    }
    { // stage B: this half's 512 codebook rows (already fp16-padded)
        const float4* e4 = (const float4*)(g_ehf + (size_t)kh * 512 * BPAD);
        float4* s4 = (float4*)(sm + OFF_B);
        #pragma unroll
        for (int u = 0; u < 9; u++) {
            int i = tid + u * 512;
            s4[i] = e4[i];
        }
    }
    // fused zero-fill: this CTA's 1/512 slice of the encodings region
    {
        float4* ez = (float4*)(out + OUT_E_OFF) + (size_t)bid * 32768 + tid;
        const float4 z = make_float4(0.f, 0.f, 0.f, 0.f);
        #pragma unroll
        for (int u = 0; u < 64; u++) __stcs(ez + u * 512, z);
    }
    __syncthreads();

    // A fragments: this warp's 16 rows
    const int rbase = warp * 16;
    uint32_t af[4][4];
    {
        int r0w = (rbase + g) * 36;
        #pragma unroll
        for (int ks = 0; ks < 4; ks++) {
            int kw = ks * 8 + tig;
            af[ks][0] = Aw[r0w + kw];
            af[ks][1] = Aw[r0w + 288 + kw];      // +8 rows
            af[ks][2] = Aw[r0w + kw + 4];
            af[ks][3] = Aw[r0w + 288 + kw + 4];
        }
    }
    uint32_t S[2][4];
    #pragma unroll
    for (int j = 0; j < 2; j++)
        #pragma unroll
        for (int p = 0; p < 4; p++) S[j][p] = 0u;

    uint32_t bA0[4], bA1[4], bB0[4], bB1[4];
    LOADB(bA0, bA1, 0);
    #pragma unroll 2
    for (int nt = 0; nt < 64; nt += 2) {
        LOADB(bB0, bB1, nt + 1);
        STEP(bA0, bA1, nt);
        if (nt + 2 < 64) LOADB(bA0, bA1, nt + 2);
        STEP(bB0, bB1, nt + 1);
    }
    // quad merge
    #pragma unroll
    for (int dd = 1; dd <= 2; dd <<= 1) {
        #pragma unroll
        for (int j = 0; j < 2; j++) {
            uint32_t ns[4];
            #pragma unroll
            for (int p = 0; p < 4; p++)
                ns[p] = __shfl_xor_sync(0xffffffffu, S[j][p], dd);
            #pragma unroll
            for (int p = 0; p < 4; p++) INSK(S[j], ns[p]);
        }
    }
    if (tig < 2) {
        const int r = rbase + g + tig * 8;
        const int n = n0 + r;
        uint32_t* Ss = S[tig];
        g_k4[kh][n] = make_uint4(Ss[0], Ss[1], Ss[2], Ss[3]);
    }
}

// ---------------- M2: merge halves + exact rescore + epilogue -------------
__global__ __launch_bounds__(128) void vq_m2(
    const float* __restrict__ xg, const float* __restrict__ emb, float* __restrict__ out)
{
    __shared__ int   sIdx[128];
    __shared__ float sW[4];
    const int tid = threadIdx.x, lane = tid & 31, warp = tid >> 5;
    const int n0 = blockIdx.x * 128;
    const int n = n0 + tid;

    // merge the two per-half sorted top-4s -> global top-4
    uint4 ka = g_k4[0][n], kb = g_k4[1][n];
    uint32_t S[4] = {ka.x, ka.y, ka.z, ka.w};
    INSK(S, kb.x); INSK(S, kb.y); INSK(S, kb.z); INSK(S, kb.w);
    const bool fb = (unpackkey(S[3]) >= unpackkey(S[0]) - MARGIN);
    int ci[4] = { 1023 - (int)(S[0] & 1023u), 1023 - (int)(S[1] & 1023u),
                  1023 - (int)(S[2] & 1023u), 1023 - (int)(S[3] & 1023u) };
    CSWP(ci[0], ci[1]); CSWP(ci[2], ci[3]);
    CSWP(ci[0], ci[2]); CSWP(ci[1], ci[3]); CSWP(ci[1], ci[2]);
    if (fb) { int sl = atomicAdd(&g_cnt, 1); g_list[sl] = n; }

    float xv[64];
    {
        const float4* xr = (const float4*)(xg + (size_t)n * D);
        #pragma unroll
        for (int j = 0; j < 16; j++) {
            float4 v = xr[j];
            xv[4*j] = v.x; xv[4*j+1] = v.y; xv[4*j+2] = v.z; xv[4*j+3] = v.w;
        }
    }
    float Av = 0.f;
    #pragma unroll
    for (int d = 0; d < D; d++) Av = fmaf(xv[d], xv[d], Av);

    // exact rescore (validated round-0 fl chain, ascending-k strict <)
    float best = CUDART_INF_F; int bidx = 0;
    #pragma unroll
    for (int q = 0; q < 4; q++) {
        int idx = ci[q];
        const float4* er = (const float4*)(emb + (size_t)idx * D);
        float a = 0.f;
        #pragma unroll
        for (int j = 0; j < 16; j++) {
            float4 v = er[j];
            a = fmaf(xv[4*j],   v.x, a);
            a = fmaf(xv[4*j+1], v.y, a);
            a = fmaf(xv[4*j+2], v.z, a);
            a = fmaf(xv[4*j+3], v.w, a);
        }
        float ddv = (Av + g_B[idx]) - 2.f * a;
        if (ddv < best) { best = ddv; bidx = idx; }
    }
    sIdx[tid] = bidx;
    g_idx[n] = bidx;
    __syncthreads();

    // quantized_st + loss: linear coalesced loop over the 128-vector tile
    float ls = 0.f;
    {
        const float4* x4 = (const float4*)(xg + (size_t)n0 * D);
        float4* qo = (float4*)(out + (size_t)n0 * D);
        #pragma unroll
        for (int it = 0; it < 16; it++) {
            int i = tid + it * 128;
            int r = i >> 4, c4 = i & 15;
            int idx = sIdx[r];
            float4 xw = x4[i];
            float4 e4 = ((const float4*)(emb + (size_t)idx * D))[c4];
            float dx = e4.x - xw.x, dy = e4.y - xw.y;
            float dz = e4.z - xw.z, dw = e4.w - xw.w;
            __stcs(&qo[i], make_float4(xw.x + dx, xw.y + dy, xw.z + dz, xw.w + dw));
            ls += dx*dx + dy*dy + dz*dz + dw*dw;
        }
    }
    #pragma unroll
    for (int o = 16; o; o >>= 1) ls += __shfl_down_sync(0xffffffffu, ls, o);
    if (lane == 0) sW[warp] = ls;
    __syncthreads();
    if (tid == 0) g_part2[blockIdx.x] = sW[0] + sW[1] + sW[2] + sW[3];
}

// ---------------- fallback: chunked smem, 1 vec/warp, MLP loads -----------
#define FCHUNK 128
#define FSTRIDE 68
#define FBLOCKS 296
__global__ __launch_bounds__(256) void vq_fallback(
    const float* __restrict__ xg, const float* __restrict__ emb, float* __restrict__ out)
{
    __shared__ float sC[FCHUNK * FSTRIDE];   // 34816B
    const int cnt = g_cnt;
    if (blockIdx.x * 8 >= cnt) return;
    const int tid = threadIdx.x, warp = tid >> 5, lane = tid & 31;
    const int nwg = FBLOCKS * 8;
    const int rounds = (cnt + nwg - 1) / nwg;
    for (int rd = 0; rd < rounds; rd++) {
        if (rd * nwg + blockIdx.x * 8 >= cnt) break;
        const int it = rd * nwg + blockIdx.x * 8 + warp;
        const bool act = it < cnt;
        const int n = act ? g_list[it] : 0;
        float xv[64];
        float Av = 0.f;
        if (act) {
            const float4* xr = (const float4*)(xg + (size_t)n * D);
            #pragma unroll
            for (int j = 0; j < 16; j++) {
                float4 v = xr[j];
                xv[4*j] = v.x; xv[4*j+1] = v.y; xv[4*j+2] = v.z; xv[4*j+3] = v.w;
            }
            #pragma unroll
            for (int d = 0; d < D; d++) Av = fmaf(xv[d], xv[d], Av);
        }
        float best = CUDART_INF_F; int bidx = 0;
        for (int ch = 0; ch < K / FCHUNK; ch++) {
            float4 ld[8];
            const float4* e4 = (const float4*)(emb + (size_t)ch * FCHUNK * D);
            #pragma unroll
            for (int u = 0; u < 8; u++) ld[u] = e4[tid + u * 256];
            __syncthreads();
            #pragma unroll
            for (int u = 0; u < 8; u++) {
                int i = tid + u * 256;
                int row = i >> 4, j = i & 15;
                *(float4*)(sC + row * FSTRIDE + j * 4) = ld[u];
            }
            __syncthreads();
            if (act) {
                #pragma unroll
                for (int cj = 0; cj < FCHUNK / 32; cj++) {
                    int c = lane + cj * 32;
                    int k = ch * FCHUNK + c;
                    const float4* er = (const float4*)(sC + c * FSTRIDE);
                    float a = 0.f;
                    #pragma unroll
                    for (int j = 0; j < 16; j++) {
                        float4 v = er[j];
                        a = fmaf(xv[4*j],   v.x, a);
                        a = fmaf(xv[4*j+1], v.y, a);
                        a = fmaf(xv[4*j+2], v.z, a);
                        a = fmaf(xv[4*j+3], v.w, a);
                    }
                    float ddv = (Av + g_B[k]) - 2.f * a;
                    if (ddv < best) { best = ddv; bidx = k; }
                }
            }
        }
        if (act) {
            unsigned long long key =
                ((unsigned long long)__float_as_uint(best) << 32) | (unsigned)bidx;
            #pragma unroll
            for (int o = 16; o; o >>= 1) {
                unsigned long long k2 = __shfl_down_sync(0xffffffffu, key, o);
                if (k2 < key) key = k2;
            }
            key = __shfl_sync(0xffffffffu, key, 0);
            const int idx = (int)(key & 0xffffffffu);
            const int old = g_idx[n];
            if (idx != old) {
                if (lane == 0) g_idx[n] = idx;
                float lsn = 0.f, lso = 0.f;
                if (lane < 16) {
                    float4 e4 = ((const float4*)(emb + (size_t)idx * D))[lane];
                    float4 o4 = ((const float4*)(emb + (size_t)old * D))[lane];
                    float xx = xv[4*lane], xy = xv[4*lane+1], xz = xv[4*lane+2], xw2 = xv[4*lane+3];
                    float dx = e4.x-xx, dy = e4.y-xy, dz = e4.z-xz, dw = e4.w-xw2;
                    ((float4*)(out + (size_t)n * D))[lane] =
                        make_float4(xx+dx, xy+dy, xz+dz, xw2+dw);
                    lsn = dx*dx + dy*dy + dz*dz + dw*dw;
                    float ox = o4.x-xx, oy = o4.y-xy, oz = o4.z-xz, ow = o4.w-xw2;
                    lso = ox*ox + oy*oy + oz*oz + ow*ow;
                }
                #pragma unroll
                for (int o = 16; o; o >>= 1) {
                    lsn += __shfl_down_sync(0xffffffffu, lsn, o);
                    lso += __shfl_down_sync(0xffffffffu, lso, o);
                }
                if (lane == 0) atomicAdd(&g_fix, lsn - lso);
            }
        }
    }
}

// ---------------- ones: scatter 1.0f at final indices ---------------------
__global__ __launch_bounds__(256) void vq_ones(float* __restrict__ out) {
    const int n = blockIdx.x * 256 + threadIdx.x;   // grid 256
    const int idx = g_idx[n];
    out[OUT_E_OFF + (size_t)n * K + idx] = 1.0f;
}

// ---------------- finalize: 512 partials + fix ----------------------------
__global__ void vq_finalize(float* __restrict__ out) {
    __shared__ double sR[256];
    int tid = threadIdx.x;   // 256
    sR[tid] = (double)g_part2[tid] + (double)g_part2[tid + 256];
    __syncthreads();
    #pragma unroll
    for (int st = 128; st; st >>= 1) {
        if (tid < st) sR[tid] += sR[tid + st];
        __syncthreads();
    }
    if (tid == 0) {
        double tot = sR[0] + (double)g_fix;
        float cb = (float)(tot / (double)((size_t)N_VEC * D));
        out[OUT_S_OFF + 0] = cb + 0.25f * cb;
        out[OUT_S_OFF + 1] = cb;
        out[OUT_S_OFF + 2] = cb;
    }
}

extern "C" void kernel_launch(void* const* d_in, const int* in_sizes, int n_in,
                              void* d_out, int out_size) {
    const float* x   = (const float*)d_in[0];
    const float* emb = (const float*)d_in[1];
    float* out = (float*)d_out;
    cudaFuncSetAttribute(vq_m1, cudaFuncAttributeMaxDynamicSharedMemorySize, SMEM_TOTAL);
    vq_prep<<<8, 128>>>(emb);
    vq_m1<<<512, 512, SMEM_TOTAL>>>(x, out);
    vq_m2<<<512, 128>>>(x, emb, out);
    vq_fallback<<<FBLOCKS, 256>>>(x, emb, out);
    vq_ones<<<N_VEC / 256, 256>>>(out);
    vq_finalize<<<1, 256>>>(out);
}

// round 17
// speedup vs baseline: 1.4364x; 1.2615x over previous
#include <cuda_runtime.h>
#include <cuda_fp16.h>
#include <cstdint>
#include <math_constants.h>

#define N_VEC 65536
#define D 64
#define K 1024
#define MARGIN 5e-5f
#define OUT_E_OFF ((size_t)N_VEC * D)
#define OUT_S_OFF (OUT_E_OFF + (size_t)N_VEC * K)

#define APAD 72                    // fp16 elems per padded row (144B)
#define BPAD 72
// M1 smem layout (per CTA, 2 CTAs/SM): sBb 2KB | A 256*144 | B 512*144
#define OFF_SBB 0
#define OFF_A   2048
#define OFF_B   (2048 + 36864)     // 38912
#define SMEM_TOTAL (OFF_B + 73728) // 112640

__device__ float  g_B[K];
__device__ __align__(16) __half g_ehf[K * BPAD];
__device__ int    g_cnt;
__device__ int    g_list[N_VEC];
__device__ int    g_idx[N_VEC];
__device__ __align__(16) uint4 g_k4[2][N_VEC];  // per-half sorted top-4 keys
__device__ float  g_part2[512];
__device__ float  g_fix;

// key: biased score (+1.0 => positive => raw-bit orderable), low 10 bits = 1023-k
__device__ __forceinline__ float unpackkey(uint32_t key) {
    return __uint_as_float(key & 0xFFFFFC00u);
}
// branchless insert into descending top-4 (7 IMNMX)
#define INSK(S, t0) { uint32_t _t = (t0), _u; \
    _u = max((S)[0], _t); _t = min((S)[0], _t); (S)[0] = _u; \
    _u = max((S)[1], _t); _t = min((S)[1], _t); (S)[1] = _u; \
    _u = max((S)[2], _t); _t = min((S)[2], _t); (S)[2] = _u; \
    (S)[3] = max((S)[3], _t); }

#define MMA(c, a, bb0, bb1) asm volatile( \
    "mma.sync.aligned.m16n8k16.row.col.f32.f16.f16.f32 " \
    "{%0,%1,%2,%3}, {%4,%5,%6,%7}, {%8,%9}, {%0,%1,%2,%3};" \
    : "+f"(c[0]), "+f"(c[1]), "+f"(c[2]), "+f"(c[3]) \
    : "r"(a[0]), "r"(a[1]), "r"(a[2]), "r"(a[3]), "r"(bb0), "r"(bb1))

#define CSWP(a, b) { if ((a) > (b)) { int _t = (a); (a) = (b); (b) = _t; } }

#define LOADB(B0, B1, NT) { \
    const int brw = ((NT) * 8 + g) * 36; \
    _Pragma("unroll") \
    for (int ks = 0; ks < 4; ks++) { \
        (B0)[ks] = Bw[brw + ks * 8 + tig]; \
        (B1)[ks] = Bw[brw + ks * 8 + tig + 4]; \
    } }

// one step: 4 MMAs in TWO independent chains, 4 scores, cheap-pack, insert
#define STEP(B0, B1, NT) { \
    float ca[4] = {0.f, 0.f, 0.f, 0.f}, cb[4] = {0.f, 0.f, 0.f, 0.f}; \
    MMA(ca, af[0], (B0)[0], (B1)[0]); \
    MMA(cb, af[1], (B0)[1], (B1)[1]); \
    MMA(ca, af[2], (B0)[2], (B1)[2]); \
    MMA(cb, af[3], (B0)[3], (B1)[3]); \
    const int k0l = (NT) * 8 + tig * 2; \
    const float2 bb = *(const float2*)(sBb + k0l); \
    const uint32_t kv0 = kvbase - (uint32_t)k0l; \
    float s; uint32_t key; \
    s = fmaf(2.f, ca[0] + cb[0], bb.x); key = (__float_as_uint(s) & 0xFFFFFC00u) | kv0;       INSK(S[0], key); \
    s = fmaf(2.f, ca[1] + cb[1], bb.y); key = (__float_as_uint(s) & 0xFFFFFC00u) | (kv0 - 1); INSK(S[0], key); \
    s = fmaf(2.f, ca[2] + cb[2], bb.x); key = (__float_as_uint(s) & 0xFFFFFC00u) | kv0;       INSK(S[1], key); \
    s = fmaf(2.f, ca[3] + cb[3], bb.y); key = (__float_as_uint(s) & 0xFFFFFC00u) | (kv0 - 1); INSK(S[1], key); }

// ---------------- prep: g_B (exact chain) + padded fp16 codebook ----------
__global__ void vq_prep(const float* __restrict__ emb) {
    int k = blockIdx.x * blockDim.x + threadIdx.x;    // 8 x 128 = 1024
    float v[D];
    const float4* r4 = (const float4*)(emb + (size_t)k * D);
    #pragma unroll
    for (int j = 0; j < 16; j++) {
        float4 t = r4[j];
        v[4*j] = t.x; v[4*j+1] = t.y; v[4*j+2] = t.z; v[4*j+3] = t.w;
    }
    float bb = 0.f;
    #pragma unroll
    for (int d = 0; d < D; d++) bb += v[d] * v[d];
    g_B[k] = bb;
    __half2* eb = (__half2*)(g_ehf + (size_t)k * BPAD);
    #pragma unroll
    for (int j = 0; j < 32; j++)
        eb[j] = __floats2half2_rn(v[2*j], v[2*j+1]);
    #pragma unroll
    for (int j = 32; j < 36; j++)
        eb[j] = __floats2half2_rn(0.f, 0.f);
    if (k == 0) { g_cnt = 0; g_fix = 0.f; }
}

// ---------------- M1: K-split HMMA prefilter + TRICKLED zero-fill ---------
// Zero-fill stores are interleaved into the MMA loop (2 STG.128 per nt-pair)
// so they slot into LSU gaps instead of damming the fragment LDS queue.
__global__ __launch_bounds__(512, 2) void vq_m1(
    const float* __restrict__ xg, float* __restrict__ out)
{
    extern __shared__ char sm[];
    float*    sBb = (float*)(sm + OFF_SBB);
    uint32_t* Aw  = (uint32_t*)(sm + OFF_A);   // 36 words per padded row
    uint32_t* Bw  = (uint32_t*)(sm + OFF_B);

    const int tid = threadIdx.x;
    const int warp = tid >> 5, lane = tid & 31;
    const int g = lane >> 2, tig = lane & 3;
    const int bid = blockIdx.x;
    const int n0 = (bid >> 1) * 256;
    const int kh = bid & 1;
    const uint32_t kvbase = 1023u - (uint32_t)(kh * 512);

    if (tid < 512) sBb[tid] = 1.0f - g_B[kh * 512 + tid];
    { // stage A: 256 rows of x -> fp16 padded
        const float4* x4 = (const float4*)(xg + (size_t)n0 * D);
        #pragma unroll
        for (int u = 0; u < 8; u++) {
            int i = tid + u * 512;
            float4 v = x4[i];
            int row = i >> 4, j = i & 15;
            __half2* p = (__half2*)((__half*)(sm + OFF_A) + row * APAD + j * 4);
            p[0] = __floats2half2_rn(v.x, v.y);
            p[1] = __floats2half2_rn(v.z, v.w);
        }
    }
    { // stage B: this half's 512 codebook rows (already fp16-padded)
        const float4* e4 = (const float4*)(g_ehf + (size_t)kh * 512 * BPAD);
        float4* s4 = (float4*)(sm + OFF_B);
        #pragma unroll
        for (int u = 0; u < 9; u++) {
            int i = tid + u * 512;
            s4[i] = e4[i];
        }
    }
    __syncthreads();

    // A fragments: this warp's 16 rows
    const int rbase = warp * 16;
    uint32_t af[4][4];
    {
        int r0w = (rbase + g) * 36;
        #pragma unroll
        for (int ks = 0; ks < 4; ks++) {
            int kw = ks * 8 + tig;
            af[ks][0] = Aw[r0w + kw];
            af[ks][1] = Aw[r0w + 288 + kw];      // +8 rows
            af[ks][2] = Aw[r0w + kw + 4];
            af[ks][3] = Aw[r0w + 288 + kw + 4];
        }
    }
    uint32_t S[2][4];
    #pragma unroll
    for (int j = 0; j < 2; j++)
        #pragma unroll
        for (int p = 0; p < 4; p++) S[j][p] = 0u;

    // zero-fill targets: this CTA's 1/512 slice of encodings
    float4* ez = (float4*)(out + OUT_E_OFF) + (size_t)bid * 32768 + tid;
    const float4 zz = make_float4(0.f, 0.f, 0.f, 0.f);

    uint32_t bA0[4], bA1[4], bB0[4], bB1[4];
    LOADB(bA0, bA1, 0);
    #pragma unroll 2
    for (int nt = 0; nt < 64; nt += 2) {
        LOADB(bB0, bB1, nt + 1);
        __stcs(ez + (size_t)nt * 512, zz);
        STEP(bA0, bA1, nt);
        if (nt + 2 < 64) LOADB(bA0, bA1, nt + 2);
        __stcs(ez + (size_t)(nt + 1) * 512, zz);
        STEP(bB0, bB1, nt + 1);
    }
    // quad merge
    #pragma unroll
    for (int dd = 1; dd <= 2; dd <<= 1) {
        #pragma unroll
        for (int j = 0; j < 2; j++) {
            uint32_t ns[4];
            #pragma unroll
            for (int p = 0; p < 4; p++)
                ns[p] = __shfl_xor_sync(0xffffffffu, S[j][p], dd);
            #pragma unroll
            for (int p = 0; p < 4; p++) INSK(S[j], ns[p]);
        }
    }
    if (tig < 2) {
        const int r = rbase + g + tig * 8;
        const int n = n0 + r;
        uint32_t* Ss = S[tig];
        g_k4[kh][n] = make_uint4(Ss[0], Ss[1], Ss[2], Ss[3]);
    }
}

// ---------------- M2: merge halves + exact rescore + epilogue + ones ------
__global__ __launch_bounds__(128) void vq_m2(
    const float* __restrict__ xg, const float* __restrict__ emb, float* __restrict__ out)
{
    __shared__ int   sIdx[128];
    __shared__ float sW[4];
    const int tid = threadIdx.x, lane = tid & 31, warp = tid >> 5;
    const int n0 = blockIdx.x * 128;
    const int n = n0 + tid;

    // merge the two per-half sorted top-4s -> global top-4
    uint4 ka = g_k4[0][n], kb = g_k4[1][n];
    uint32_t S[4] = {ka.x, ka.y, ka.z, ka.w};
    INSK(S, kb.x); INSK(S, kb.y); INSK(S, kb.z); INSK(S, kb.w);
    const bool fb = (unpackkey(S[3]) >= unpackkey(S[0]) - MARGIN);
    int ci[4] = { 1023 - (int)(S[0] & 1023u), 1023 - (int)(S[1] & 1023u),
                  1023 - (int)(S[2] & 1023u), 1023 - (int)(S[3] & 1023u) };
    CSWP(ci[0], ci[1]); CSWP(ci[2], ci[3]);
    CSWP(ci[0], ci[2]); CSWP(ci[1], ci[3]); CSWP(ci[1], ci[2]);
    if (fb) { int sl = atomicAdd(&g_cnt, 1); g_list[sl] = n; }

    float xv[64];
    {
        const float4* xr = (const float4*)(xg + (size_t)n * D);
        #pragma unroll
        for (int j = 0; j < 16; j++) {
            float4 v = xr[j];
            xv[4*j] = v.x; xv[4*j+1] = v.y; xv[4*j+2] = v.z; xv[4*j+3] = v.w;
        }
    }
    float Av = 0.f;
    #pragma unroll
    for (int d = 0; d < D; d++) Av = fmaf(xv[d], xv[d], Av);

    // exact rescore (validated round-0 fl chain, ascending-k strict <)
    float best = CUDART_INF_F; int bidx = 0;
    #pragma unroll
    for (int q = 0; q < 4; q++) {
        int idx = ci[q];
        const float4* er = (const float4*)(emb + (size_t)idx * D);
        float a = 0.f;
        #pragma unroll
        for (int j = 0; j < 16; j++) {
            float4 v = er[j];
            a = fmaf(xv[4*j],   v.x, a);
            a = fmaf(xv[4*j+1], v.y, a);
            a = fmaf(xv[4*j+2], v.z, a);
            a = fmaf(xv[4*j+3], v.w, a);
        }
        float ddv = (Av + g_B[idx]) - 2.f * a;
        if (ddv < best) { best = ddv; bidx = idx; }
    }
    sIdx[tid] = bidx;
    g_idx[n] = bidx;
    // one-hot "1": final for non-fb vectors (fb vectors written by fallback)
    if (!fb) out[OUT_E_OFF + (size_t)n * K + bidx] = 1.0f;
    __syncthreads();

    // quantized_st + loss: linear coalesced loop over the 128-vector tile
    float ls = 0.f;
    {
        const float4* x4 = (const float4*)(xg + (size_t)n0 * D);
        float4* qo = (float4*)(out + (size_t)n0 * D);
        #pragma unroll
        for (int it = 0; it < 16; it++) {
            int i = tid + it * 128;
            int r = i >> 4, c4 = i & 15;
            int idx = sIdx[r];
            float4 xw = x4[i];
            float4 e4 = ((const float4*)(emb + (size_t)idx * D))[c4];
            float dx = e4.x - xw.x, dy = e4.y - xw.y;
            float dz = e4.z - xw.z, dw = e4.w - xw.w;
            __stcs(&qo[i], make_float4(xw.x + dx, xw.y + dy, xw.z + dz, xw.w + dw));
            ls += dx*dx + dy*dy + dz*dz + dw*dw;
        }
    }
    #pragma unroll
    for (int o = 16; o; o >>= 1) ls += __shfl_down_sync(0xffffffffu, ls, o);
    if (lane == 0) sW[warp] = ls;
    __syncthreads();
    if (tid == 0) g_part2[blockIdx.x] = sW[0] + sW[1] + sW[2] + sW[3];
}

// ---------------- fallback: double-buffered chunked smem scan -------------
#define FCHUNK 128
#define FSTRIDE 68
#define FBLOCKS 296
#define FB_SMEM (2 * FCHUNK * FSTRIDE * 4)   // 69632 bytes
__global__ __launch_bounds__(256) void vq_fallback(
    const float* __restrict__ xg, const float* __restrict__ emb, float* __restrict__ out)
{
    extern __shared__ float sC[];            // [2][FCHUNK*FSTRIDE]
    const int cnt = g_cnt;
    if (blockIdx.x * 8 >= cnt) return;
    const int tid = threadIdx.x, warp = tid >> 5, lane = tid & 31;
    const int nwg = FBLOCKS * 8;
    const int rounds = (cnt + nwg - 1) / nwg;
    for (int rd = 0; rd < rounds; rd++) {
        if (rd * nwg + blockIdx.x * 8 >= cnt) break;
        const int it = rd * nwg + blockIdx.x * 8 + warp;
        const bool act = it < cnt;
        const int n = act ? g_list[it] : 0;
        float xv[64];
        float Av = 0.f;
        if (act) {
            const float4* xr = (const float4*)(xg + (size_t)n * D);
            #pragma unroll
            for (int j = 0; j < 16; j++) {
                float4 v = xr[j];
                xv[4*j] = v.x; xv[4*j+1] = v.y; xv[4*j+2] = v.z; xv[4*j+3] = v.w;
            }
            #pragma unroll
            for (int d = 0; d < D; d++) Av = fmaf(xv[d], xv[d], Av);
        }
        float best = CUDART_INF_F; int bidx = 0;
        // prefetch chunk 0
        float4 ld[8];
        {
            const float4* e4 = (const float4*)emb;
            #pragma unroll
            for (int u = 0; u < 8; u++) ld[u] = e4[tid + u * 256];
        }
        for (int ch = 0; ch < K / FCHUNK; ch++) {
            float* buf = sC + (ch & 1) * (FCHUNK * FSTRIDE);
            __syncthreads();   // buf's previous scan (iter ch-2) complete
            #pragma unroll
            for (int u = 0; u < 8; u++) {
                int i = tid + u * 256;
                *(float4*)(buf + (i >> 4) * FSTRIDE + (i & 15) * 4) = ld[u];
            }
            __syncthreads();
            // prefetch next chunk while scanning this one
            if (ch + 1 < K / FCHUNK) {
                const float4* e4 = (const float4*)(emb + (size_t)(ch + 1) * FCHUNK * D);
                #pragma unroll
                for (int u = 0; u < 8; u++) ld[u] = e4[tid + u * 256];
            }
            if (act) {
                #pragma unroll
                for (int cj = 0; cj < FCHUNK / 32; cj++) {
                    int c = lane + cj * 32;
                    int k = ch * FCHUNK + c;
                    const float4* er = (const float4*)(buf + c * FSTRIDE);
                    float a = 0.f;
                    #pragma unroll
                    for (int j = 0; j < 16; j++) {
                        float4 v = er[j];
                        a = fmaf(xv[4*j],   v.x, a);
                        a = fmaf(xv[4*j+1], v.y, a);
                        a = fmaf(xv[4*j+2], v.z, a);
                        a = fmaf(xv[4*j+3], v.w, a);
                    }
                    float ddv = (Av + g_B[k]) - 2.f * a;
                    if (ddv < best) { best = ddv; bidx = k; }
                }
            }
        }
        if (act) {
            unsigned long long key =
                ((unsigned long long)__float_as_uint(best) << 32) | (unsigned)bidx;
            #pragma unroll
            for (int o = 16; o; o >>= 1) {
                unsigned long long k2 = __shfl_down_sync(0xffffffffu, key, o);
                if (k2 < key) key = k2;
            }
            key = __shfl_sync(0xffffffffu, key, 0);
            const int idx = (int)(key & 0xffffffffu);
            const int old = g_idx[n];
            // one-hot "1" for this fb vector (zeros laid down in M1; M2 skipped it)
            if (lane == 0) out[OUT_E_OFF + (size_t)n * K + idx] = 1.0f;
            if (idx != old) {
                if (lane == 0) g_idx[n] = idx;
                float lsn = 0.f, lso = 0.f;
                if (lane < 16) {
                    float4 e4 = ((const float4*)(emb + (size_t)idx * D))[lane];
                    float4 o4 = ((const float4*)(emb + (size_t)old * D))[lane];
                    float xx = xv[4*lane], xy = xv[4*lane+1], xz = xv[4*lane+2], xw2 = xv[4*lane+3];
                    float dx = e4.x-xx, dy = e4.y-xy, dz = e4.z-xz, dw = e4.w-xw2;
                    ((float4*)(out + (size_t)n * D))[lane] =
                        make_float4(xx+dx, xy+dy, xz+dz, xw2+dw);
                    lsn = dx*dx + dy*dy + dz*dz + dw*dw;
                    float ox = o4.x-xx, oy = o4.y-xy, oz = o4.z-xz, ow = o4.w-xw2;
                    lso = ox*ox + oy*oy + oz*oz + ow*ow;
                }
                #pragma unroll
                for (int o = 16; o; o >>= 1) {
                    lsn += __shfl_down_sync(0xffffffffu, lsn, o);
                    lso += __shfl_down_sync(0xffffffffu, lso, o);
                }
                if (lane == 0) atomicAdd(&g_fix, lsn - lso);
            }
        }
    }
}

// ---------------- finalize: 512 partials + fix ----------------------------
__global__ void vq_finalize(float* __restrict__ out) {
    __shared__ double sR[256];
    int tid = threadIdx.x;   // 256
    sR[tid] = (double)g_part2[tid] + (double)g_part2[tid + 256];
    __syncthreads();
    #pragma unroll
    for (int st = 128; st; st >>= 1) {
        if (tid < st) sR[tid] += sR[tid + st];
        __syncthreads();
    }
    if (tid == 0) {
        double tot = sR[0] + (double)g_fix;
        float cb = (float)(tot / (double)((size_t)N_VEC * D));
        out[OUT_S_OFF + 0] = cb + 0.25f * cb;
        out[OUT_S_OFF + 1] = cb;
        out[OUT_S_OFF + 2] = cb;
    }
}

extern "C" void kernel_launch(void* const* d_in, const int* in_sizes, int n_in,
                              void* d_out, int out_size) {
    const float* x   = (const float*)d_in[0];
    const float* emb = (const float*)d_in[1];
    float* out = (float*)d_out;
    cudaFuncSetAttribute(vq_m1, cudaFuncAttributeMaxDynamicSharedMemorySize, SMEM_TOTAL);
    cudaFuncSetAttribute(vq_fallback, cudaFuncAttributeMaxDynamicSharedMemorySize, FB_SMEM);
    vq_prep<<<8, 128>>>(emb);
    vq_m1<<<512, 512, SMEM_TOTAL>>>(x, out);
    vq_m2<<<512, 128>>>(x, emb, out);
    vq_fallback<<<FBLOCKS, 256, FB_SMEM>>>(x, emb, out);
    vq_finalize<<<1, 256>>>(out);
}